// round 14
// baseline (speedup 1.0000x reference)
#include <cuda_runtime.h>
#include <cuda_bf16.h>

#define BB 8
#define NN 2048
#define DD 128

// 1/(2*sqrt(128)): reference scales A by 1/sqrt(D) then entmax divides by 2.
// Folded into Q at projection epilogue.
#define ENTMAX_SCALE 0.04419417382415922f

// Static scratch (no alloc allowed): split-bf16 Q/K and fp32 logits.
__device__ __nv_bfloat16 g_Qh[BB * NN * DD];
__device__ __nv_bfloat16 g_Ql[BB * NN * DD];
__device__ __nv_bfloat16 g_Kh[BB * NN * DD];
__device__ __nv_bfloat16 g_Kl[BB * NN * DD];
__device__ float        g_A[(long)BB * NN * NN];   // 134 MB raw logits

__device__ __forceinline__ unsigned smem_u32(const void* p) {
    unsigned a;
    asm("{ .reg .u64 t; cvta.to.shared.u64 t, %1; cvt.u32.u64 %0, t; }"
        : "=r"(a) : "l"(p));
    return a;
}

#define LDSM_X4(r0, r1, r2, r3, addr) \
    asm volatile("ldmatrix.sync.aligned.m8n8.x4.shared.b16 {%0,%1,%2,%3}, [%4];" \
                 : "=r"(r0), "=r"(r1), "=r"(r2), "=r"(r3) : "r"(addr))

#define MMA_BF16(c, a0, a1, a2, a3, b0, b1) \
    asm volatile("mma.sync.aligned.m16n8k16.row.col.f32.bf16.bf16.f32 " \
                 "{%0,%1,%2,%3}, {%4,%5,%6,%7}, {%8,%9}, {%0,%1,%2,%3};" \
                 : "+f"((c)[0]), "+f"((c)[1]), "+f"((c)[2]), "+f"((c)[3]) \
                 : "r"(a0), "r"(a1), "r"(a2), "r"(a3), "r"(b0), "r"(b1))

// Shared tile geometry
#define PITCH_B 272                  // bytes per 128-half row (17x16B: ldsm conflict-free)
#define T_BYTES (128 * PITCH_B)      // 34816 per 128-row tile
#define H_BYTES (64 * PITCH_B)       // 17408 per 64-row tile
#define P_SMEM  (4 * T_BYTES + 512)  // proj: 4 tiles + bias

// qk smem: Q 64-row (hi+lo) + K 128-row (hi+lo) = 104448 -> 2 CTAs/SM
#define SM_QH   0
#define SM_QL   (H_BYTES)
#define SM_KH   (2 * H_BYTES)
#define SM_KL   (2 * H_BYTES + T_BYTES)
#define QK_SMEM (2 * H_BYTES + 2 * T_BYTES)

// ---------------------------------------------------------------------------
// Split a float4 into hi/lo bf16x2 pairs (packed as uint2 for 8B smem stores)
// ---------------------------------------------------------------------------
__device__ __forceinline__ void split4(float4 v, uint2& hh, uint2& ll)
{
    __nv_bfloat162 pa = __floats2bfloat162_rn(v.x, v.y);
    __nv_bfloat162 pb = __floats2bfloat162_rn(v.z, v.w);
    __nv_bfloat162 la = __floats2bfloat162_rn(v.x - __low2float(pa),
                                              v.y - __high2float(pa));
    __nv_bfloat162 lb = __floats2bfloat162_rn(v.z - __low2float(pb),
                                              v.w - __high2float(pb));
    hh.x = *reinterpret_cast<unsigned*>(&pa);
    hh.y = *reinterpret_cast<unsigned*>(&pb);
    ll.x = *reinterpret_cast<unsigned*>(&la);
    ll.y = *reinterpret_cast<unsigned*>(&lb);
}

// ---------------------------------------------------------------------------
// Kernel 1: projection via split-bf16 HMMA (unchanged; measured 25.7 us).
// ---------------------------------------------------------------------------
#define SM_AH   0
#define SM_AL   (T_BYTES)
#define SM_BH   (2 * T_BYTES)
#define SM_BL   (3 * T_BYTES)
#define SM_BIAS (4 * T_BYTES)

__global__ void __launch_bounds__(256, 1)
proj_mma_kernel(const float* __restrict__ x_c,
                const float* __restrict__ x_n,
                const float* __restrict__ Wq,
                const float* __restrict__ bq,
                const float* __restrict__ Wk,
                const float* __restrict__ bk)
{
    extern __shared__ char smem[];
    const unsigned sb = smem_u32(smem);
    const int tid  = threadIdx.x;
    const int wid  = tid >> 5;
    const int lane = tid & 31;
    const int wm   = (wid & 3) * 32;
    const int wn   = (wid >> 2) * 64;

    const int which = (blockIdx.x >= 128);
    const int row0  = (blockIdx.x & 127) * 128;
    const float* x    = which ? x_n : x_c;
    const float* W    = which ? Wk  : Wq;
    const float* bias = which ? bk  : bq;
    __nv_bfloat16* oh = which ? g_Kh : g_Qh;
    __nv_bfloat16* ol = which ? g_Kl : g_Ql;
    const float scale = which ? 1.0f : ENTMAX_SCALE;

    {
        const float4* xs = (const float4*)(x + (long)row0 * DD);
        const float4* ws = (const float4*)W;
        #pragma unroll
        for (int i = 0; i < 16; i++) {
            int idx = i * 256 + tid;
            int r = idx >> 5, c4 = idx & 31;
            uint2 hh, ll;
            split4(xs[idx], hh, ll);
            *(uint2*)(smem + SM_AH + r * PITCH_B + c4 * 8) = hh;
            *(uint2*)(smem + SM_AL + r * PITCH_B + c4 * 8) = ll;
            split4(ws[idx], hh, ll);
            *(uint2*)(smem + SM_BH + r * PITCH_B + c4 * 8) = hh;
            *(uint2*)(smem + SM_BL + r * PITCH_B + c4 * 8) = ll;
        }
        if (tid < 128) ((float*)(smem + SM_BIAS))[tid] = bias[tid];
    }
    __syncthreads();

    float acc[2][8][4];
    #pragma unroll
    for (int mt = 0; mt < 2; mt++)
        #pragma unroll
        for (int nt = 0; nt < 8; nt++)
            #pragma unroll
            for (int j = 0; j < 4; j++) acc[mt][nt][j] = 0.f;

    const int lrow = lane & 15;
    const int lcol = (lane >> 4) * 8;

    #pragma unroll
    for (int pass = 0; pass < 3; pass++) {
        const int aoff = (pass == 2) ? SM_AL : SM_AH;
        const int boff = (pass == 1) ? SM_BL : SM_BH;

        unsigned a[2][8][4];
        #pragma unroll
        for (int mt = 0; mt < 2; mt++)
            #pragma unroll
            for (int kt = 0; kt < 8; kt++) {
                unsigned addr = sb + aoff + (wm + mt * 16 + lrow) * PITCH_B
                              + (kt * 16 + lcol) * 2;
                LDSM_X4(a[mt][kt][0], a[mt][kt][1], a[mt][kt][2], a[mt][kt][3], addr);
            }

        #pragma unroll
        for (int ntp = 0; ntp < 4; ntp++) {
            #pragma unroll
            for (int kt = 0; kt < 8; kt++) {
                unsigned b0, b1, b2, b3;
                unsigned addr = sb + boff + (wn + ntp * 16 + lrow) * PITCH_B
                              + (kt * 16 + lcol) * 2;
                LDSM_X4(b0, b1, b2, b3, addr);
                #pragma unroll
                for (int mt = 0; mt < 2; mt++) {
                    MMA_BF16(acc[mt][2 * ntp + 0], a[mt][kt][0], a[mt][kt][1],
                             a[mt][kt][2], a[mt][kt][3], b0, b2);
                    MMA_BF16(acc[mt][2 * ntp + 1], a[mt][kt][0], a[mt][kt][1],
                             a[mt][kt][2], a[mt][kt][3], b1, b3);
                }
            }
        }
    }

    const int crow = lane >> 2;
    const int ccol = (lane & 3) * 2;
    const float* bs = (const float*)(smem + SM_BIAS);
    #pragma unroll
    for (int mt = 0; mt < 2; mt++)
        #pragma unroll
        for (int nt = 0; nt < 8; nt++) {
            int col = wn + nt * 8 + ccol;
            float b0 = bs[col], b1 = bs[col + 1];
            #pragma unroll
            for (int half = 0; half < 2; half++) {
                long row = row0 + wm + mt * 16 + crow + half * 8;
                float v0 = (acc[mt][nt][2 * half + 0] + b0) * scale;
                float v1 = (acc[mt][nt][2 * half + 1] + b1) * scale;
                __nv_bfloat162 ph = __floats2bfloat162_rn(v0, v1);
                __nv_bfloat162 pl = __floats2bfloat162_rn(v0 - __low2float(ph),
                                                          v1 - __high2float(ph));
                *(__nv_bfloat162*)(oh + row * DD + col) = ph;
                *(__nv_bfloat162*)(ol + row * DD + col) = pl;
            }
        }
}

// ---------------------------------------------------------------------------
// Kernel 2: split-bf16 HMMA GEMM, SMALL TILES for 2 CTAs/SM.
// CTA: 256 threads (8 warps, 4x2), tile M=64 x N=128, K=128 resident.
// 32 consecutive CTAs share one K tile (L2-hot). Batch-sliced (bbase).
// ---------------------------------------------------------------------------
__device__ __forceinline__ void stage_async(unsigned sdst,
                                            const __nv_bfloat16* src,
                                            int tid, int n16)
{
    for (int i = 0; i < n16; i++) {
        int idx = i * 256 + tid;                 // idx = row*16 + c8
        int row = idx >> 4, c8 = idx & 15;
        unsigned dst = sdst + row * PITCH_B + c8 * 16;
        asm volatile("cp.async.cg.shared.global [%0], [%1], 16;"
                     :: "r"(dst), "l"((const char*)src + (long)idx * 16) : "memory");
    }
}

__global__ void __launch_bounds__(256, 2)
qk_mma_kernel(int bbase)
{
    extern __shared__ char smem[];
    const unsigned sb = smem_u32(smem);
    const int tid  = threadIdx.x;
    const int wid  = tid >> 5;
    const int lane = tid & 31;
    const int wm   = (wid & 3) * 16;             // warp M offset within 64
    const int wn   = (wid >> 2) * 64;            // warp N offset within 128

    // 512 CTAs per batch; consecutive 32 share the same K tile (same b, n0).
    const int b   = bbase + (blockIdx.x >> 9);
    const int rem = blockIdx.x & 511;
    const int n0  = (rem >> 5) << 7;
    const int m0  = (rem & 31) << 6;

    const long qb = (long)(b * NN + m0) * DD;
    const long kb = (long)(b * NN + n0) * DD;
    stage_async(sb + SM_QH, g_Qh + qb, tid, 4);
    stage_async(sb + SM_QL, g_Ql + qb, tid, 4);
    stage_async(sb + SM_KH, g_Kh + kb, tid, 8);
    stage_async(sb + SM_KL, g_Kl + kb, tid, 8);
    asm volatile("cp.async.commit_group;" ::: "memory");
    asm volatile("cp.async.wait_group 0;" ::: "memory");
    __syncthreads();

    float acc[8][4];
    #pragma unroll
    for (int q = 0; q < 8; q++)
        #pragma unroll
        for (int j = 0; j < 4; j++) acc[q][j] = 0.f;

    const int lrow = lane & 15;
    const int lcol = (lane >> 4) * 8;

    // Qh fragments resident across passes 0 and 1.
    unsigned AH[8][4];
    #pragma unroll
    for (int kt = 0; kt < 8; kt++) {
        unsigned addr = sb + SM_QH + (wm + lrow) * PITCH_B + (kt * 16 + lcol) * 2;
        LDSM_X4(AH[kt][0], AH[kt][1], AH[kt][2], AH[kt][3], addr);
    }

    #pragma unroll
    for (int pass = 0; pass < 3; pass++) {
        const int koff = (pass == 1) ? SM_KL : SM_KH;
        #pragma unroll
        for (int kt = 0; kt < 8; kt++) {
            unsigned a0, a1, a2, a3;
            if (pass < 2) {
                a0 = AH[kt][0]; a1 = AH[kt][1]; a2 = AH[kt][2]; a3 = AH[kt][3];
            } else {
                unsigned addr = sb + SM_QL + (wm + lrow) * PITCH_B
                              + (kt * 16 + lcol) * 2;
                LDSM_X4(a0, a1, a2, a3, addr);
            }
            #pragma unroll
            for (int ntp = 0; ntp < 4; ntp++) {
                unsigned b0, b1, b2, b3;
                unsigned addr = sb + koff + (wn + ntp * 16 + lrow) * PITCH_B
                              + (kt * 16 + lcol) * 2;
                LDSM_X4(b0, b1, b2, b3, addr);
                MMA_BF16(acc[2 * ntp + 0], a0, a1, a2, a3, b0, b2);
                MMA_BF16(acc[2 * ntp + 1], a0, a1, a2, a3, b1, b3);
            }
        }
    }

    const int crow = lane >> 2;
    const int ccol = (lane & 3) * 2;
    float* base = g_A + (long)(b * NN + m0 + wm) * NN + n0 + wn;
    #pragma unroll
    for (int q = 0; q < 8; q++) {
        float* p0 = base + (long)crow * NN + q * 8 + ccol;
        *(float2*)p0              = make_float2(acc[q][0], acc[q][1]);
        *(float2*)(p0 + 8LL * NN) = make_float2(acc[q][2], acc[q][3]);
    }
}

// ---------------------------------------------------------------------------
// Kernel 3: 1.5-entmax per row (sort-free monotone Newton), batch-sliced
// to read the logit slab while it is still L2-resident.
// ---------------------------------------------------------------------------
__global__ void __launch_bounds__(256)
entmax_kernel(float* __restrict__ out, int bbase)
{
    const int tid = threadIdx.x;
    const int tx  = tid & 31;
    const int wy  = tid >> 5;
    const long row = (long)(bbase + (blockIdx.x >> 8)) * NN
                   + (blockIdx.x & 255) * 8 + wy;

    const float4* src = (const float4*)(g_A + row * NN);
    float acc[64];
    float zmax = -1e30f;
    #pragma unroll
    for (int t = 0; t < 16; t++) {
        float4 v = src[t * 32 + tx];
        acc[t*4+0] = v.x; acc[t*4+1] = v.y; acc[t*4+2] = v.z; acc[t*4+3] = v.w;
        zmax = fmaxf(zmax, fmaxf(fmaxf(v.x, v.y), fmaxf(v.z, v.w)));
    }
    #pragma unroll
    for (int o = 16; o; o >>= 1)
        zmax = fmaxf(zmax, __shfl_xor_sync(0xffffffffu, zmax, o));
    #pragma unroll
    for (int i = 0; i < 64; i++) acc[i] -= zmax;

    // tau = root of f(tau) = sum((z-tau)_+^2) - 1 (convex, decreasing);
    // monotone Newton from tau=-1 never overshoots.
    float tau = -1.0f;
    for (int it = 0; it < 50; it++) {
        float s1 = 0.f, s2 = 0.f;
        #pragma unroll
        for (int i = 0; i < 64; i++) {
            float d = fmaxf(acc[i] - tau, 0.f);
            s1 += d;
            s2 = fmaf(d, d, s2);
        }
        #pragma unroll
        for (int o = 16; o; o >>= 1) {
            s1 += __shfl_xor_sync(0xffffffffu, s1, o);
            s2 += __shfl_xor_sync(0xffffffffu, s2, o);
        }
        float f = s2 - 1.0f;
        if (f < 1e-5f) break;
        tau += f / (2.0f * s1);
    }

    float4* dst = (float4*)(out + row * NN);
    #pragma unroll
    for (int t = 0; t < 16; t++) {
        float d0 = fmaxf(acc[t*4+0] - tau, 0.f);
        float d1 = fmaxf(acc[t*4+1] - tau, 0.f);
        float d2 = fmaxf(acc[t*4+2] - tau, 0.f);
        float d3 = fmaxf(acc[t*4+3] - tau, 0.f);
        dst[t * 32 + tx] = make_float4(d0*d0, d1*d1, d2*d2, d3*d3);
    }
}

// ---------------------------------------------------------------------------
extern "C" void kernel_launch(void* const* d_in, const int* in_sizes, int n_in,
                              void* d_out, int out_size)
{
    const float* x_c = (const float*)d_in[0];
    const float* x_n = (const float*)d_in[1];
    const float* Wq  = (const float*)d_in[2];
    const float* bq  = (const float*)d_in[3];
    const float* Wk  = (const float*)d_in[4];
    const float* bk  = (const float*)d_in[5];

    cudaFuncSetAttribute(proj_mma_kernel,
                         cudaFuncAttributeMaxDynamicSharedMemorySize, P_SMEM);
    cudaFuncSetAttribute(qk_mma_kernel,
                         cudaFuncAttributeMaxDynamicSharedMemorySize, QK_SMEM);

    proj_mma_kernel<<<256, 256, P_SMEM>>>(x_c, x_n, Wq, bq, Wk, bk);

    // 2 slices of 4 batches: each slice's 67 MB logit slab fits in the
    // 126 MB L2, so the entmax read is served from L2, not DRAM.
    for (int s = 0; s < 2; s++) {
        qk_mma_kernel<<<4 * 512, 256, QK_SMEM>>>(s * 4);
        entmax_kernel<<<4 * 256, 256>>>((float*)d_out, s * 4);
    }
}

// round 15
// speedup vs baseline: 1.4458x; 1.4458x over previous
#include <cuda_runtime.h>
#include <cuda_bf16.h>

#define BB 8
#define NN 2048
#define DD 128

// 1/(2*sqrt(128)): reference scales A by 1/sqrt(D) then entmax divides by 2.
// Folded into Q at projection epilogue.
#define ENTMAX_SCALE 0.04419417382415922f

// Static scratch (no alloc allowed): split-bf16 Q/K and fp32 logits.
__device__ __nv_bfloat16 g_Qh[BB * NN * DD];
__device__ __nv_bfloat16 g_Ql[BB * NN * DD];
__device__ __nv_bfloat16 g_Kh[BB * NN * DD];
__device__ __nv_bfloat16 g_Kl[BB * NN * DD];
__device__ float        g_A[(long)BB * NN * NN];   // 134 MB raw logits

__device__ __forceinline__ unsigned smem_u32(const void* p) {
    unsigned a;
    asm("{ .reg .u64 t; cvta.to.shared.u64 t, %1; cvt.u32.u64 %0, t; }"
        : "=r"(a) : "l"(p));
    return a;
}

#define LDSM_X4(r0, r1, r2, r3, addr) \
    asm volatile("ldmatrix.sync.aligned.m8n8.x4.shared.b16 {%0,%1,%2,%3}, [%4];" \
                 : "=r"(r0), "=r"(r1), "=r"(r2), "=r"(r3) : "r"(addr))

#define MMA_BF16(c, a0, a1, a2, a3, b0, b1) \
    asm volatile("mma.sync.aligned.m16n8k16.row.col.f32.bf16.bf16.f32 " \
                 "{%0,%1,%2,%3}, {%4,%5,%6,%7}, {%8,%9}, {%0,%1,%2,%3};" \
                 : "+f"((c)[0]), "+f"((c)[1]), "+f"((c)[2]), "+f"((c)[3]) \
                 : "r"(a0), "r"(a1), "r"(a2), "r"(a3), "r"(b0), "r"(b1))

// Shared tile geometry
#define PITCH_B 272                  // bytes per 128-half row (17x16B: ldsm conflict-free)
#define T_BYTES (128 * PITCH_B)      // 34816 per 128-row tile
#define QT_BYTES (256 * PITCH_B)     // 69632 per 256-row tile
#define P_SMEM  (4 * T_BYTES + 512)  // proj: 4 tiles + bias

// qk smem: Q 256-row (hi+lo) + K 128-row (hi+lo) = 208896 -> 1 CTA/SM, 16 warps
#define SM_QH   0
#define SM_QL   (QT_BYTES)
#define SM_KH   (2 * QT_BYTES)
#define SM_KL   (2 * QT_BYTES + T_BYTES)
#define QK_SMEM (2 * QT_BYTES + 2 * T_BYTES)

// ---------------------------------------------------------------------------
// Split a float4 into hi/lo bf16x2 pairs (packed as uint2 for 8B smem stores)
// ---------------------------------------------------------------------------
__device__ __forceinline__ void split4(float4 v, uint2& hh, uint2& ll)
{
    __nv_bfloat162 pa = __floats2bfloat162_rn(v.x, v.y);
    __nv_bfloat162 pb = __floats2bfloat162_rn(v.z, v.w);
    __nv_bfloat162 la = __floats2bfloat162_rn(v.x - __low2float(pa),
                                              v.y - __high2float(pa));
    __nv_bfloat162 lb = __floats2bfloat162_rn(v.z - __low2float(pb),
                                              v.w - __high2float(pb));
    hh.x = *reinterpret_cast<unsigned*>(&pa);
    hh.y = *reinterpret_cast<unsigned*>(&pb);
    ll.x = *reinterpret_cast<unsigned*>(&la);
    ll.y = *reinterpret_cast<unsigned*>(&lb);
}

// ---------------------------------------------------------------------------
// Kernel 1: projection via split-bf16 HMMA (unchanged; measured 25.7 us).
// ---------------------------------------------------------------------------
#define SM_AH   0
#define SM_AL   (T_BYTES)
#define SM_BH   (2 * T_BYTES)
#define SM_BL   (3 * T_BYTES)
#define SM_BIAS (4 * T_BYTES)

__global__ void __launch_bounds__(256, 1)
proj_mma_kernel(const float* __restrict__ x_c,
                const float* __restrict__ x_n,
                const float* __restrict__ Wq,
                const float* __restrict__ bq,
                const float* __restrict__ Wk,
                const float* __restrict__ bk)
{
    extern __shared__ char smem[];
    const unsigned sb = smem_u32(smem);
    const int tid  = threadIdx.x;
    const int wid  = tid >> 5;
    const int lane = tid & 31;
    const int wm   = (wid & 3) * 32;
    const int wn   = (wid >> 2) * 64;

    const int which = (blockIdx.x >= 128);
    const int row0  = (blockIdx.x & 127) * 128;
    const float* x    = which ? x_n : x_c;
    const float* W    = which ? Wk  : Wq;
    const float* bias = which ? bk  : bq;
    __nv_bfloat16* oh = which ? g_Kh : g_Qh;
    __nv_bfloat16* ol = which ? g_Kl : g_Ql;
    const float scale = which ? 1.0f : ENTMAX_SCALE;

    {
        const float4* xs = (const float4*)(x + (long)row0 * DD);
        const float4* ws = (const float4*)W;
        #pragma unroll
        for (int i = 0; i < 16; i++) {
            int idx = i * 256 + tid;
            int r = idx >> 5, c4 = idx & 31;
            uint2 hh, ll;
            split4(xs[idx], hh, ll);
            *(uint2*)(smem + SM_AH + r * PITCH_B + c4 * 8) = hh;
            *(uint2*)(smem + SM_AL + r * PITCH_B + c4 * 8) = ll;
            split4(ws[idx], hh, ll);
            *(uint2*)(smem + SM_BH + r * PITCH_B + c4 * 8) = hh;
            *(uint2*)(smem + SM_BL + r * PITCH_B + c4 * 8) = ll;
        }
        if (tid < 128) ((float*)(smem + SM_BIAS))[tid] = bias[tid];
    }
    __syncthreads();

    float acc[2][8][4];
    #pragma unroll
    for (int mt = 0; mt < 2; mt++)
        #pragma unroll
        for (int nt = 0; nt < 8; nt++)
            #pragma unroll
            for (int j = 0; j < 4; j++) acc[mt][nt][j] = 0.f;

    const int lrow = lane & 15;
    const int lcol = (lane >> 4) * 8;

    #pragma unroll
    for (int pass = 0; pass < 3; pass++) {
        const int aoff = (pass == 2) ? SM_AL : SM_AH;
        const int boff = (pass == 1) ? SM_BL : SM_BH;

        unsigned a[2][8][4];
        #pragma unroll
        for (int mt = 0; mt < 2; mt++)
            #pragma unroll
            for (int kt = 0; kt < 8; kt++) {
                unsigned addr = sb + aoff + (wm + mt * 16 + lrow) * PITCH_B
                              + (kt * 16 + lcol) * 2;
                LDSM_X4(a[mt][kt][0], a[mt][kt][1], a[mt][kt][2], a[mt][kt][3], addr);
            }

        #pragma unroll
        for (int ntp = 0; ntp < 4; ntp++) {
            #pragma unroll
            for (int kt = 0; kt < 8; kt++) {
                unsigned b0, b1, b2, b3;
                unsigned addr = sb + boff + (wn + ntp * 16 + lrow) * PITCH_B
                              + (kt * 16 + lcol) * 2;
                LDSM_X4(b0, b1, b2, b3, addr);
                #pragma unroll
                for (int mt = 0; mt < 2; mt++) {
                    MMA_BF16(acc[mt][2 * ntp + 0], a[mt][kt][0], a[mt][kt][1],
                             a[mt][kt][2], a[mt][kt][3], b0, b2);
                    MMA_BF16(acc[mt][2 * ntp + 1], a[mt][kt][0], a[mt][kt][1],
                             a[mt][kt][2], a[mt][kt][3], b1, b3);
                }
            }
        }
    }

    const int crow = lane >> 2;
    const int ccol = (lane & 3) * 2;
    const float* bs = (const float*)(smem + SM_BIAS);
    #pragma unroll
    for (int mt = 0; mt < 2; mt++)
        #pragma unroll
        for (int nt = 0; nt < 8; nt++) {
            int col = wn + nt * 8 + ccol;
            float b0 = bs[col], b1 = bs[col + 1];
            #pragma unroll
            for (int half = 0; half < 2; half++) {
                long row = row0 + wm + mt * 16 + crow + half * 8;
                float v0 = (acc[mt][nt][2 * half + 0] + b0) * scale;
                float v1 = (acc[mt][nt][2 * half + 1] + b1) * scale;
                __nv_bfloat162 ph = __floats2bfloat162_rn(v0, v1);
                __nv_bfloat162 pl = __floats2bfloat162_rn(v0 - __low2float(ph),
                                                          v1 - __high2float(ph));
                *(__nv_bfloat162*)(oh + row * DD + col) = ph;
                *(__nv_bfloat162*)(ol + row * DD + col) = pl;
            }
        }
}

// ---------------------------------------------------------------------------
// Kernel 2: split-bf16 HMMA GEMM, BIG CTA: 512 threads (16 warps, 8x2),
// tile M=256 x N=128, K=128 resident. 1 CTA/SM, 2x K-reuse vs r8.
// Consecutive 8 CTAs share one K tile (L2-hot). Batch-sliced (bbase).
// ---------------------------------------------------------------------------
__device__ __forceinline__ void stage_async(unsigned sdst,
                                            const __nv_bfloat16* src,
                                            int tid, int n16)
{
    for (int i = 0; i < n16; i++) {
        int idx = i * 512 + tid;                 // idx = row*16 + c8
        int row = idx >> 4, c8 = idx & 15;
        unsigned dst = sdst + row * PITCH_B + c8 * 16;
        asm volatile("cp.async.cg.shared.global [%0], [%1], 16;"
                     :: "r"(dst), "l"((const char*)src + (long)idx * 16) : "memory");
    }
}

__global__ void __launch_bounds__(512, 1)
qk_mma_kernel(int bbase)
{
    extern __shared__ char smem[];
    const unsigned sb = smem_u32(smem);
    const int tid  = threadIdx.x;
    const int wid  = tid >> 5;
    const int lane = tid & 31;
    const int wm   = (wid & 7) * 32;             // warp M offset within 256
    const int wn   = (wid >> 3) * 64;            // warp N offset within 128

    // 128 CTAs per batch; consecutive 8 share the same K tile (same b, n0).
    const int b   = bbase + (blockIdx.x >> 7);
    const int rem = blockIdx.x & 127;
    const int n0  = (rem >> 3) << 7;
    const int m0  = (rem & 7) << 8;

    const long qb = (long)(b * NN + m0) * DD;
    const long kb = (long)(b * NN + n0) * DD;
    stage_async(sb + SM_QH, g_Qh + qb, tid, 8);   // 256 rows
    stage_async(sb + SM_QL, g_Ql + qb, tid, 8);
    stage_async(sb + SM_KH, g_Kh + kb, tid, 4);   // 128 rows
    stage_async(sb + SM_KL, g_Kl + kb, tid, 4);
    asm volatile("cp.async.commit_group;" ::: "memory");
    asm volatile("cp.async.wait_group 0;" ::: "memory");
    __syncthreads();

    float acc[2][8][4];
    #pragma unroll
    for (int mt = 0; mt < 2; mt++)
        #pragma unroll
        for (int q = 0; q < 8; q++)
            #pragma unroll
            for (int j = 0; j < 4; j++) acc[mt][q][j] = 0.f;

    const int lrow = lane & 15;
    const int lcol = (lane >> 4) * 8;

    #pragma unroll
    for (int pass = 0; pass < 3; pass++) {
        const int aoff = (pass == 2) ? SM_QL : SM_QH;
        const int koff = (pass == 1) ? SM_KL : SM_KH;

        unsigned a[2][8][4];
        #pragma unroll
        for (int mt = 0; mt < 2; mt++)
            #pragma unroll
            for (int kt = 0; kt < 8; kt++) {
                unsigned addr = sb + aoff + (wm + mt * 16 + lrow) * PITCH_B
                              + (kt * 16 + lcol) * 2;
                LDSM_X4(a[mt][kt][0], a[mt][kt][1], a[mt][kt][2], a[mt][kt][3], addr);
            }

        #pragma unroll
        for (int ntp = 0; ntp < 4; ntp++) {
            #pragma unroll
            for (int kt = 0; kt < 8; kt++) {
                unsigned b0, b1, b2, b3;
                unsigned addr = sb + koff + (wn + ntp * 16 + lrow) * PITCH_B
                              + (kt * 16 + lcol) * 2;
                LDSM_X4(b0, b1, b2, b3, addr);
                #pragma unroll
                for (int mt = 0; mt < 2; mt++) {
                    MMA_BF16(acc[mt][2 * ntp + 0], a[mt][kt][0], a[mt][kt][1],
                             a[mt][kt][2], a[mt][kt][3], b0, b2);
                    MMA_BF16(acc[mt][2 * ntp + 1], a[mt][kt][0], a[mt][kt][1],
                             a[mt][kt][2], a[mt][kt][3], b1, b3);
                }
            }
        }
    }

    const int crow = lane >> 2;
    const int ccol = (lane & 3) * 2;
    float* base = g_A + (long)(b * NN + m0 + wm) * NN + n0 + wn;
    #pragma unroll
    for (int mt = 0; mt < 2; mt++)
        #pragma unroll
        for (int q = 0; q < 8; q++) {
            float* p0 = base + (long)(mt * 16 + crow) * NN + q * 8 + ccol;
            *(float2*)p0              = make_float2(acc[mt][q][0], acc[mt][q][1]);
            *(float2*)(p0 + 8LL * NN) = make_float2(acc[mt][q][2], acc[mt][q][3]);
        }
}

// ---------------------------------------------------------------------------
// Kernel 3: 1.5-entmax per row (sort-free monotone Newton), batch-sliced
// to read the logit slab while it is still L2-resident.
// ---------------------------------------------------------------------------
__global__ void __launch_bounds__(256)
entmax_kernel(float* __restrict__ out, int bbase)
{
    const int tid = threadIdx.x;
    const int tx  = tid & 31;
    const int wy  = tid >> 5;
    const long row = (long)(bbase + (blockIdx.x >> 8)) * NN
                   + (blockIdx.x & 255) * 8 + wy;

    const float4* src = (const float4*)(g_A + row * NN);
    float acc[64];
    float zmax = -1e30f;
    #pragma unroll
    for (int t = 0; t < 16; t++) {
        float4 v = src[t * 32 + tx];
        acc[t*4+0] = v.x; acc[t*4+1] = v.y; acc[t*4+2] = v.z; acc[t*4+3] = v.w;
        zmax = fmaxf(zmax, fmaxf(fmaxf(v.x, v.y), fmaxf(v.z, v.w)));
    }
    #pragma unroll
    for (int o = 16; o; o >>= 1)
        zmax = fmaxf(zmax, __shfl_xor_sync(0xffffffffu, zmax, o));
    #pragma unroll
    for (int i = 0; i < 64; i++) acc[i] -= zmax;

    // tau = root of f(tau) = sum((z-tau)_+^2) - 1 (convex, decreasing);
    // monotone Newton from tau=-1 never overshoots.
    float tau = -1.0f;
    for (int it = 0; it < 50; it++) {
        float s1 = 0.f, s2 = 0.f;
        #pragma unroll
        for (int i = 0; i < 64; i++) {
            float d = fmaxf(acc[i] - tau, 0.f);
            s1 += d;
            s2 = fmaf(d, d, s2);
        }
        #pragma unroll
        for (int o = 16; o; o >>= 1) {
            s1 += __shfl_xor_sync(0xffffffffu, s1, o);
            s2 += __shfl_xor_sync(0xffffffffu, s2, o);
        }
        float f = s2 - 1.0f;
        if (f < 1e-5f) break;
        tau += f / (2.0f * s1);
    }

    float4* dst = (float4*)(out + row * NN);
    #pragma unroll
    for (int t = 0; t < 16; t++) {
        float d0 = fmaxf(acc[t*4+0] - tau, 0.f);
        float d1 = fmaxf(acc[t*4+1] - tau, 0.f);
        float d2 = fmaxf(acc[t*4+2] - tau, 0.f);
        float d3 = fmaxf(acc[t*4+3] - tau, 0.f);
        dst[t * 32 + tx] = make_float4(d0*d0, d1*d1, d2*d2, d3*d3);
    }
}

// ---------------------------------------------------------------------------
extern "C" void kernel_launch(void* const* d_in, const int* in_sizes, int n_in,
                              void* d_out, int out_size)
{
    const float* x_c = (const float*)d_in[0];
    const float* x_n = (const float*)d_in[1];
    const float* Wq  = (const float*)d_in[2];
    const float* bq  = (const float*)d_in[3];
    const float* Wk  = (const float*)d_in[4];
    const float* bk  = (const float*)d_in[5];

    cudaFuncSetAttribute(proj_mma_kernel,
                         cudaFuncAttributeMaxDynamicSharedMemorySize, P_SMEM);
    cudaFuncSetAttribute(qk_mma_kernel,
                         cudaFuncAttributeMaxDynamicSharedMemorySize, QK_SMEM);

    proj_mma_kernel<<<256, 256, P_SMEM>>>(x_c, x_n, Wq, bq, Wk, bk);

    // 2 slices of 4 batches: each slice's 67 MB logit slab fits in the
    // 126 MB L2, so the entmax read is served from L2, not DRAM.
    for (int s = 0; s < 2; s++) {
        qk_mma_kernel<<<4 * 128, 512, QK_SMEM>>>(s * 4);
        entmax_kernel<<<4 * 256, 256>>>((float*)d_out, s * 4);
    }
}